// round 3
// baseline (speedup 1.0000x reference)
#include <cuda_runtime.h>
#include <cuda_bf16.h>
#include <math.h>

// ---------------- problem constants ----------------
#define S    256
#define Dm   2048
#define NH   16
#define DH   128
#define MLPD 8192
#define INPUT_D 4096
#define EPS  1e-5f

// ---------------- scratch ----------------
__device__ float g_x  [S * Dm];
__device__ float g_h  [S * Dm];
__device__ float g_q  [S * Dm];
__device__ float g_k  [S * Dm];
__device__ float g_v  [S * Dm];
__device__ float g_att[NH * S * S];
__device__ float g_m  [S * MLPD];
__device__ float g_split[2 * S * Dm];

// ---------------- bf16 split-2 tensor-core GEMM ----------------
// x = hi + lo (bf16 each); C += Ah*Bh + Al*Bh + Ah*Bl  -> ~16-bit mantissa accuracy
// Tiles: 64x128x32, 256 threads (8 warps, 2x4), warp tile 32x32.
#define BM 64
#define BN 128
#define BK 32
#define LDW 20   // u32 words per smem row (= 40 bf16: 32 data + 8 pad; 20%32 bijective frags)

__device__ __forceinline__ float bhi(float x) {
    return __bfloat162float(__float2bfloat16(x));
}
__device__ __forceinline__ unsigned pack2(float a, float b) {
    __nv_bfloat162 t = __floats2bfloat162_rn(a, b);
    return *(unsigned*)&t;
}
__device__ __forceinline__ void mma_bf16(float* c, const unsigned* a, const unsigned* b) {
    asm volatile(
        "mma.sync.aligned.m16n8k16.row.col.f32.bf16.bf16.f32 "
        "{%0,%1,%2,%3}, {%4,%5,%6,%7}, {%8,%9}, {%0,%1,%2,%3};\n"
        : "+f"(c[0]), "+f"(c[1]), "+f"(c[2]), "+f"(c[3])
        : "r"(a[0]), "r"(a[1]), "r"(a[2]), "r"(a[3]), "r"(b[0]), "r"(b[1]));
}

// modes: 0 store | 1 store+posemb | 2 gelu | 3 accumulate | -1 raw (split-K)
__global__ __launch_bounds__(256) void tgemm_k(
    const float* __restrict__ A, const float* __restrict__ B, float* __restrict__ C,
    int M, int N, int K, int lda, int ldb, int ldc,
    long batchA, long batchB, long batchC,
    const float* __restrict__ bias, long biasBatch,
    float scale, int mode, int transB, int splitK,
    int qkv, const float* __restrict__ B1, const float* __restrict__ B2,
    float* C1, float* C2,
    const float* __restrict__ bias1, const float* __restrict__ bias2)
{
    __shared__ unsigned AsH[BM * LDW], AsL[BM * LDW];
    __shared__ unsigned BsH[BN * LDW], BsL[BN * LDW];

    int z = blockIdx.z;
    if (qkv) {
        const int sel = z >> 4;
        z &= 15;
        if (sel == 1)      { B = B1; C = C1; bias = bias1; }
        else if (sel == 2) { B = B2; C = C2; bias = bias2; }
    }
    if (splitK > 1) {
        const int Kc = K / splitK;
        A += (long)z * Kc;
        B += transB ? (long)z * Kc : (long)z * Kc * ldb;
        C += (long)z * M * N;
        ldc = N; K = Kc; bias = nullptr; mode = -1;
    } else {
        A += (long)z * batchA;
        B += (long)z * batchB;
        C += (long)z * batchC;
        if (bias) bias += (long)z * biasBatch;
    }

    const int m0 = blockIdx.y * BM;
    const int n0 = blockIdx.x * BN;
    const int tid  = threadIdx.x;
    const int lane = tid & 31;
    const int warp = tid >> 5;
    const int wm = warp >> 2;          // 0..1
    const int wn = warp & 3;           // 0..3
    const int lr = lane >> 2;          // 0..7
    const int lc = lane & 3;           // 0..3

    float acc[2][4][4];
    #pragma unroll
    for (int i = 0; i < 2; i++)
        #pragma unroll
        for (int j = 0; j < 4; j++)
            #pragma unroll
            for (int r = 0; r < 4; r++) acc[i][j][r] = 0.f;

    // staging indices
    const int aRow0 = tid >> 3;          // 0..31 (+32)
    const int aKq   = (tid & 7) << 2;
    const int bKrow = tid >> 5;          // 0..7 (+8i), transB=0
    const int bNq   = (tid & 31) << 2;
    const int bTn0  = tid >> 3;          // 0..31 (+32i), transB=1
    const int bTkq  = (tid & 7) << 2;

    float4 ra[2], rb[4];
    const int nK = K / BK;

    // ---- prologue: load tile 0 ----
    #pragma unroll
    for (int i = 0; i < 2; i++)
        ra[i] = *(const float4*)(A + (long)(m0 + aRow0 + 32 * i) * lda + aKq);
    if (!transB) {
        #pragma unroll
        for (int i = 0; i < 4; i++)
            rb[i] = *(const float4*)(B + (long)(bKrow + 8 * i) * ldb + n0 + bNq);
    } else {
        #pragma unroll
        for (int i = 0; i < 4; i++)
            rb[i] = *(const float4*)(B + (long)(n0 + bTn0 + 32 * i) * ldb + bTkq);
    }

    for (int kt = 0; kt < nK; kt++) {
        __syncthreads();
        // ---- convert & store to smem ----
        #pragma unroll
        for (int i = 0; i < 2; i++) {
            const float4 v = ra[i];
            const int w = (aRow0 + 32 * i) * LDW + (aKq >> 1);
            uint2 hw, lw;
            hw.x = pack2(v.x, v.y);               hw.y = pack2(v.z, v.w);
            lw.x = pack2(v.x - bhi(v.x), v.y - bhi(v.y));
            lw.y = pack2(v.z - bhi(v.z), v.w - bhi(v.w));
            *(uint2*)&AsH[w] = hw;
            *(uint2*)&AsL[w] = lw;
        }
        if (!transB) {
            __nv_bfloat16* BH = (__nv_bfloat16*)BsH;
            __nv_bfloat16* BL = (__nv_bfloat16*)BsL;
            #pragma unroll
            for (int i = 0; i < 4; i++) {
                const float4 v = rb[i];
                const int krow = bKrow + 8 * i;
                const float f[4] = {v.x, v.y, v.z, v.w};
                #pragma unroll
                for (int j = 0; j < 4; j++) {
                    const int o = (bNq + j) * (2 * LDW) + krow;
                    BH[o] = __float2bfloat16(f[j]);
                    BL[o] = __float2bfloat16(f[j] - bhi(f[j]));
                }
            }
        } else {
            #pragma unroll
            for (int i = 0; i < 4; i++) {
                const float4 v = rb[i];
                const int w = (bTn0 + 32 * i) * LDW + (bTkq >> 1);
                uint2 hw, lw;
                hw.x = pack2(v.x, v.y);               hw.y = pack2(v.z, v.w);
                lw.x = pack2(v.x - bhi(v.x), v.y - bhi(v.y));
                lw.y = pack2(v.z - bhi(v.z), v.w - bhi(v.w));
                *(uint2*)&BsH[w] = hw;
                *(uint2*)&BsL[w] = lw;
            }
        }
        __syncthreads();

        // ---- prefetch next tile ----
        if (kt + 1 < nK) {
            const int k0 = (kt + 1) * BK;
            #pragma unroll
            for (int i = 0; i < 2; i++)
                ra[i] = *(const float4*)(A + (long)(m0 + aRow0 + 32 * i) * lda + k0 + aKq);
            if (!transB) {
                #pragma unroll
                for (int i = 0; i < 4; i++)
                    rb[i] = *(const float4*)(B + (long)(k0 + bKrow + 8 * i) * ldb + n0 + bNq);
            } else {
                #pragma unroll
                for (int i = 0; i < 4; i++)
                    rb[i] = *(const float4*)(B + (long)(n0 + bTn0 + 32 * i) * ldb + k0 + bTkq);
            }
        }

        // ---- compute: 2 ksteps of k=16 ----
        #pragma unroll
        for (int s = 0; s < 2; s++) {
            unsigned aH[2][4], aL[2][4], bH[4][2], bL[4][2];
            const int wb = 8 * s + lc;
            #pragma unroll
            for (int mt = 0; mt < 2; mt++) {
                const int r0 = (wm * 32 + mt * 16 + lr) * LDW;
                const int r1 = r0 + 8 * LDW;
                aH[mt][0] = AsH[r0 + wb];     aH[mt][1] = AsH[r1 + wb];
                aH[mt][2] = AsH[r0 + wb + 4]; aH[mt][3] = AsH[r1 + wb + 4];
                aL[mt][0] = AsL[r0 + wb];     aL[mt][1] = AsL[r1 + wb];
                aL[mt][2] = AsL[r0 + wb + 4]; aL[mt][3] = AsL[r1 + wb + 4];
            }
            #pragma unroll
            for (int nt = 0; nt < 4; nt++) {
                const int cn = (wn * 32 + nt * 8 + lr) * LDW;
                bH[nt][0] = BsH[cn + wb]; bH[nt][1] = BsH[cn + wb + 4];
                bL[nt][0] = BsL[cn + wb]; bL[nt][1] = BsL[cn + wb + 4];
            }
            #pragma unroll
            for (int mt = 0; mt < 2; mt++)
                #pragma unroll
                for (int nt = 0; nt < 4; nt++) {
                    mma_bf16(acc[mt][nt], aH[mt], bH[nt]);
                    mma_bf16(acc[mt][nt], aL[mt], bH[nt]);
                    mma_bf16(acc[mt][nt], aH[mt], bL[nt]);
                }
        }
    }

    // ---- epilogue ----
    #pragma unroll
    for (int mt = 0; mt < 2; mt++) {
        #pragma unroll
        for (int nt = 0; nt < 4; nt++) {
            #pragma unroll
            for (int half = 0; half < 2; half++) {
                const int r = m0 + wm * 32 + mt * 16 + lr + half * 8;
                const int cbase = n0 + wn * 32 + nt * 8 + lc * 2;
                #pragma unroll
                for (int j = 0; j < 2; j++) {
                    const int n = cbase + j;
                    const float raw = acc[mt][nt][half * 2 + j];
                    float* cp = C + (long)r * ldc + n;
                    if (mode == -1) { *cp = raw; continue; }
                    float val = raw * scale + (bias ? bias[n] : 0.0f);
                    if (mode == 0) *cp = val;
                    else if (mode == 1) {
                        const int   even = ((n & 1) == 0);
                        const float expo = (even ? (float)n : (float)(n - 1)) / (float)Dm;
                        const float ang  = (float)r / powf(10000.0f, expo);
                        *cp = val + (even ? sinf(ang) : cosf(ang));
                    } else if (mode == 2) {
                        *cp = 0.5f * val * (1.0f + erff(val * 0.70710678118654752f));
                    } else {
                        *cp += val;
                    }
                }
            }
        }
    }
}

// ---------------- split-K reduce + epilogue ----------------
__global__ __launch_bounds__(256) void reduce_k(
    const float* __restrict__ part, float* __restrict__ C,
    const float* __restrict__ bias, int M, int N, int ldc,
    int splitK, float scale, int mode)
{
    const int idx = blockIdx.x * 256 + threadIdx.x;
    if (idx >= M * N) return;
    const int m = idx / N;
    const int n = idx - m * N;
    float s = 0.f;
    for (int p = 0; p < splitK; p++) s += part[(long)p * M * N + idx];
    float val = s * scale + (bias ? bias[n] : 0.0f);
    float* cp = C + (long)m * ldc + n;
    if (mode == 0) *cp = val;
    else if (mode == 1) {
        const int   even = ((n & 1) == 0);
        const float expo = (even ? (float)n : (float)(n - 1)) / (float)Dm;
        const float ang  = (float)m / powf(10000.0f, expo);
        *cp = val + (even ? sinf(ang) : cosf(ang));
    } else if (mode == 2) {
        *cp = 0.5f * val * (1.0f + erff(val * 0.70710678118654752f));
    } else {
        *cp += val;
    }
}

// ---------------- layernorm ----------------
__global__ __launch_bounds__(256) void layernorm_k(
    const float* __restrict__ x, float* __restrict__ y,
    const float* __restrict__ g, const float* __restrict__ b)
{
    const int row = blockIdx.x;
    const float* xr = x + (long)row * Dm;
    const int t = threadIdx.x;
    __shared__ float red[256];

    float loc[8];
    float s = 0.f;
    #pragma unroll
    for (int i = 0; i < 8; i++) { loc[i] = xr[t + i * 256]; s += loc[i]; }
    red[t] = s; __syncthreads();
    for (int st = 128; st > 0; st >>= 1) { if (t < st) red[t] += red[t + st]; __syncthreads(); }
    const float mean = red[0] * (1.0f / Dm);
    __syncthreads();

    float vs = 0.f;
    #pragma unroll
    for (int i = 0; i < 8; i++) { float d = loc[i] - mean; vs += d * d; }
    red[t] = vs; __syncthreads();
    for (int st = 128; st > 0; st >>= 1) { if (t < st) red[t] += red[t + st]; __syncthreads(); }
    const float inv = rsqrtf(red[0] * (1.0f / Dm) + EPS);

    float* yr = y + (long)row * Dm;
    #pragma unroll
    for (int i = 0; i < 8; i++) {
        const int c = t + i * 256;
        yr[c] = (loc[i] - mean) * inv * g[c] + b[c];
    }
}

// ---------------- softmax (rows of 256) ----------------
__global__ __launch_bounds__(256) void softmax_k(float* __restrict__ att)
{
    const int row = blockIdx.x;
    float* p = att + (long)row * 256;
    const int t = threadIdx.x;
    __shared__ float red[256];

    float v = p[t];
    red[t] = v; __syncthreads();
    for (int st = 128; st > 0; st >>= 1) { if (t < st) red[t] = fmaxf(red[t], red[t + st]); __syncthreads(); }
    const float mx = red[0];
    __syncthreads();

    float e = expf(v - mx);
    red[t] = e; __syncthreads();
    for (int st = 128; st > 0; st >>= 1) { if (t < st) red[t] += red[t + st]; __syncthreads(); }
    p[t] = e / red[0];
}

// ---------------- head ----------------
__global__ __launch_bounds__(256) void head_k(
    const float* __restrict__ x, const float* __restrict__ hw,
    const float* __restrict__ hb, const float* __restrict__ mem,
    float* __restrict__ out, int memN)
{
    const int t = threadIdx.x;
    __shared__ float red[256];
    float s = 0.f;
    for (int i = t; i < Dm; i += 256) s += x[i] * hw[i];
    red[t] = s; __syncthreads();
    for (int st = 128; st > 0; st >>= 1) { if (t < st) red[t] += red[t + st]; __syncthreads(); }
    if (t == 0) {
        float zv = red[0] + hb[0];
        out[0] = 1.0f / (1.0f + expf(-zv));
    }
    if (t >= 1 && t <= memN) out[t] = mem[t - 1];
}

// ---------------- host launcher ----------------
static inline float* symaddr(const void* sym) {
    void* p = nullptr;
    cudaGetSymbolAddress(&p, sym);
    return (float*)p;
}

extern "C" void kernel_launch(void* const* d_in, const int* in_sizes, int n_in,
                              void* d_out, int out_size)
{
    const float* images = (const float*)d_in[0];
    const float* memory = (const float*)d_in[1];
    const float* wmap   = (const float*)d_in[2];
    const float* bmap   = (const float*)d_in[3];
    const float* ln1_g  = (const float*)d_in[4];
    const float* ln1_b  = (const float*)d_in[5];
    const float* qw     = (const float*)d_in[6];
    const float* qb     = (const float*)d_in[7];
    const float* kw     = (const float*)d_in[8];
    const float* kb     = (const float*)d_in[9];
    const float* vw     = (const float*)d_in[10];
    const float* vb     = (const float*)d_in[11];
    const float* ln2_g  = (const float*)d_in[12];
    const float* ln2_b  = (const float*)d_in[13];
    const float* w1     = (const float*)d_in[14];
    const float* b1     = (const float*)d_in[15];
    const float* w2     = (const float*)d_in[16];
    const float* b2     = (const float*)d_in[17];
    const float* head_w = (const float*)d_in[18];
    const float* head_b = (const float*)d_in[19];
    float* out = (float*)d_out;

    float* x   = symaddr(g_x);
    float* h   = symaddr(g_h);
    float* q   = symaddr(g_q);
    float* k   = symaddr(g_k);
    float* v   = symaddr(g_v);
    float* att = symaddr(g_att);
    float* m   = symaddr(g_m);
    float* ws  = symaddr(g_split);

    const float attScale = 1.0f / sqrtf((float)DH);

    // ---- patch embed (split-K=2) ----
    tgemm_k<<<dim3(Dm / BN, S / BM, 2), 256>>>(
        images, wmap, ws, S, Dm, INPUT_D, INPUT_D, Dm, Dm,
        0, 0, 0, nullptr, 0, 1.0f, 0, 0, 2,
        0, nullptr, nullptr, nullptr, nullptr, nullptr, nullptr);
    reduce_k<<<(S * Dm + 255) / 256, 256>>>(ws, x, bmap, S, Dm, Dm, 2, 1.0f, 1);

    for (int l = 0; l < 2; l++) {
        const long wOff  = (long)l * NH * DH * DH;
        const long bOff  = (long)l * Dm;
        const long w1Off = (long)l * Dm * MLPD;
        const long w2Off = (long)l * MLPD * Dm;

        layernorm_k<<<S, 256>>>(x, h, ln1_g + bOff, ln1_b + bOff);

        // fused q,k,v: grid.z = 48 (16 heads x 3 matrices)
        tgemm_k<<<dim3(DH / BN, S / BM, 3 * NH), 256>>>(
            h, qw + wOff, q, S, DH, DH, Dm, DH, Dm,
            DH, (long)DH * DH, DH, qb + bOff, DH, 1.0f, 0, 0, 1,
            1, kw + wOff, vw + wOff, k, v, kb + bOff, vb + bOff);

        // scores = q @ k^T / sqrt(DH)
        tgemm_k<<<dim3(S / BN, S / BM, NH), 256>>>(
            q, k, att, S, S, DH, Dm, Dm, S,
            DH, DH, (long)S * S, nullptr, 0, attScale, 0, 1, 1,
            0, nullptr, nullptr, nullptr, nullptr, nullptr, nullptr);

        softmax_k<<<NH * S, 256>>>(att);

        // x += att @ v
        tgemm_k<<<dim3(DH / BN, S / BM, NH), 256>>>(
            att, v, x, S, DH, S, S, Dm, Dm,
            (long)S * S, DH, DH, nullptr, 0, 1.0f, 3, 0, 1,
            0, nullptr, nullptr, nullptr, nullptr, nullptr, nullptr);

        layernorm_k<<<S, 256>>>(x, h, ln2_g + bOff, ln2_b + bOff);

        // m = gelu(h @ w1 + b1)
        tgemm_k<<<dim3(MLPD / BN, S / BM, 1), 256>>>(
            h, w1 + w1Off, m, S, MLPD, Dm, Dm, MLPD, MLPD,
            0, 0, 0, b1 + (long)l * MLPD, 0, 1.0f, 2, 0, 1,
            0, nullptr, nullptr, nullptr, nullptr, nullptr, nullptr);

        // x += m @ w2 + b2  (split-K=2)
        tgemm_k<<<dim3(Dm / BN, S / BM, 2), 256>>>(
            m, w2 + w2Off, ws, S, Dm, MLPD, MLPD, Dm, Dm,
            0, 0, 0, nullptr, 0, 1.0f, 0, 0, 2,
            0, nullptr, nullptr, nullptr, nullptr, nullptr, nullptr);
        reduce_k<<<(S * Dm + 255) / 256, 256>>>(ws, x, b2 + bOff, S, Dm, Dm, 2, 1.0f, 3);
    }

    int memN = in_sizes[1];
    if (memN > out_size - 1) memN = out_size - 1;
    head_k<<<1, 256>>>(x, head_w, head_b, memory, out, memN);
}

// round 4
// speedup vs baseline: 2.2939x; 2.2939x over previous
#include <cuda_runtime.h>
#include <cuda_bf16.h>
#include <math.h>

// ---------------- problem constants ----------------
#define S    256
#define Dm   2048
#define NH   16
#define DH   128
#define MLPD 8192
#define INPUT_D 4096
#define EPS  1e-5f

// ---------------- scratch ----------------
__device__ float g_x  [S * Dm];
__device__ float g_h  [S * Dm];
__device__ float g_q  [S * Dm];
__device__ float g_k  [S * Dm];
__device__ float g_v  [S * Dm];
__device__ float g_att[NH * S * S];
__device__ float g_m  [S * MLPD];
__device__ float g_split[4 * S * Dm];

// ---------------- bf16 split-2 tensor-core GEMM ----------------
// x = hi + lo (bf16); C += Ah*Bh + Al*Bh + Ah*Bl  (~16-bit mantissa)
// Tile 128x128x32, 256 threads (8 warps 2x4), warp tile 64x32, m16n8k16.
// Double-buffered smem, vectorized stores, register-staged prefetch.
#define BM 128
#define BN 128
#define BK 32
#define LDWA 20     // u32 words per A row (16 data + 4 pad); 20%32=4 -> frag-bijective
#define LDWB 136    // u32 words per B kp-row (128 data + 8 pad); 136%32=8 -> bijective
#define A_BUF_W (128 * LDWA)   // 2560
#define B_BUF_W (16  * LDWB)   // 2176
#define SMEM_WORDS (2*A_BUF_W*2 + 2*B_BUF_W*2)  // 18944 words = 75776 B

__device__ __forceinline__ float bhi(float x) {
    return __bfloat162float(__float2bfloat16(x));
}
__device__ __forceinline__ unsigned pack2(float a, float b) {
    __nv_bfloat162 t = __floats2bfloat162_rn(a, b);
    return *(unsigned*)&t;
}
__device__ __forceinline__ unsigned packlo(float a, float b) {
    return pack2(a - bhi(a), b - bhi(b));
}
__device__ __forceinline__ void mma_bf16(float* c, const unsigned* a, const unsigned* b) {
    asm volatile(
        "mma.sync.aligned.m16n8k16.row.col.f32.bf16.bf16.f32 "
        "{%0,%1,%2,%3}, {%4,%5,%6,%7}, {%8,%9}, {%0,%1,%2,%3};\n"
        : "+f"(c[0]), "+f"(c[1]), "+f"(c[2]), "+f"(c[3])
        : "r"(a[0]), "r"(a[1]), "r"(a[2]), "r"(a[3]), "r"(b[0]), "r"(b[1]));
}

// modes: 0 store | 1 store+posemb | 2 gelu | 3 accumulate | -1 raw (split-K)
__global__ void __launch_bounds__(256, 1) tgemm_k(
    const float* __restrict__ A, const float* __restrict__ B, float* __restrict__ C,
    int M, int N, int K, int lda, int ldb, int ldc,
    long batchA, long batchB, long batchC,
    const float* __restrict__ bias, long biasBatch,
    float scale, int mode, int transB, int splitK,
    int qkv, const float* __restrict__ B1, const float* __restrict__ B2,
    float* C1, float* C2,
    const float* __restrict__ bias1, const float* __restrict__ bias2)
{
    extern __shared__ unsigned sm[];
    unsigned* AsH = sm;                     // [2][A_BUF_W]
    unsigned* AsL = sm + 2 * A_BUF_W;
    unsigned* BsH = sm + 4 * A_BUF_W;       // [2][B_BUF_W]
    unsigned* BsL = sm + 4 * A_BUF_W + 2 * B_BUF_W;

    int z = blockIdx.z;
    if (qkv) {
        const int sel = z >> 4;
        z &= 15;
        if (sel == 1)      { B = B1; C = C1; bias = bias1; }
        else if (sel == 2) { B = B2; C = C2; bias = bias2; }
    }
    if (splitK > 1) {
        const int Kc = K / splitK;
        A += (long)z * Kc;
        B += transB ? (long)z * Kc : (long)z * Kc * ldb;
        C += (long)z * M * N;
        ldc = N; K = Kc; bias = nullptr; mode = -1;
    } else {
        A += (long)z * batchA;
        B += (long)z * batchB;
        C += (long)z * batchC;
        if (bias) bias += (long)z * biasBatch;
    }

    const int m0 = blockIdx.y * BM;
    const int n0 = blockIdx.x * BN;
    const int tid  = threadIdx.x;
    const int lane = tid & 31;
    const int warp = tid >> 5;
    const int wm = warp >> 2;          // 0..1 (64 rows each)
    const int wn = warp & 3;           // 0..3 (32 cols each)
    const int lr = lane >> 2;          // 0..7
    const int lc = lane & 3;           // 0..3

    float acc[4][4][4];
    #pragma unroll
    for (int i = 0; i < 4; i++)
        #pragma unroll
        for (int j = 0; j < 4; j++)
            #pragma unroll
            for (int r = 0; r < 4; r++) acc[i][j][r] = 0.f;

    // staging indices
    const int aRow = tid >> 1;           // 0..127
    const int aK0  = (tid & 1) << 4;     // 0 or 16
    const int bNq  = tid & 31;           // transB=0: n quad
    const int bKr0 = (tid >> 5) << 2;    // transB=0: first of 4 k rows
    const int bTn  = tid >> 1;           // transB=1: n row
    const int bTk0 = (tid & 1) << 4;     // transB=1: k start

    float4 ra[4], rb[4];
    const int nK = K / BK;

    // ---- prologue: load tile 0 into regs ----
    #pragma unroll
    for (int i = 0; i < 4; i++)
        ra[i] = *(const float4*)(A + (long)(m0 + aRow) * lda + aK0 + 4 * i);
    if (!transB) {
        #pragma unroll
        for (int i = 0; i < 4; i++)
            rb[i] = *(const float4*)(B + (long)(bKr0 + i) * ldb + n0 + (bNq << 2));
    } else {
        #pragma unroll
        for (int i = 0; i < 4; i++)
            rb[i] = *(const float4*)(B + (long)(n0 + bTn) * ldb + bTk0 + 4 * i);
    }

    // ---- convert+store tile 0 -> buf 0 ----
    {
        const float* f = (const float*)ra;
        unsigned* dH = AsH + aRow * LDWA + (aK0 >> 1);
        unsigned* dL = AsL + aRow * LDWA + (aK0 >> 1);
        *(uint4*)dH       = make_uint4(pack2(f[0],f[1]), pack2(f[2],f[3]), pack2(f[4],f[5]), pack2(f[6],f[7]));
        *(uint4*)(dH + 4) = make_uint4(pack2(f[8],f[9]), pack2(f[10],f[11]), pack2(f[12],f[13]), pack2(f[14],f[15]));
        *(uint4*)dL       = make_uint4(packlo(f[0],f[1]), packlo(f[2],f[3]), packlo(f[4],f[5]), packlo(f[6],f[7]));
        *(uint4*)(dL + 4) = make_uint4(packlo(f[8],f[9]), packlo(f[10],f[11]), packlo(f[12],f[13]), packlo(f[14],f[15]));
        if (!transB) {
            const int kp0 = bKr0 >> 1;
            #pragma unroll
            for (int p = 0; p < 2; p++) {
                float4 u = rb[2*p], v = rb[2*p+1];
                *(uint4*)(BsH + (kp0 + p) * LDWB + (bNq << 2)) =
                    make_uint4(pack2(u.x,v.x), pack2(u.y,v.y), pack2(u.z,v.z), pack2(u.w,v.w));
                *(uint4*)(BsL + (kp0 + p) * LDWB + (bNq << 2)) =
                    make_uint4(packlo(u.x,v.x), packlo(u.y,v.y), packlo(u.z,v.z), packlo(u.w,v.w));
            }
        } else {
            const float* g = (const float*)rb;
            #pragma unroll
            for (int j = 0; j < 8; j++) {
                BsH[((bTk0 >> 1) + j) * LDWB + bTn] = pack2(g[2*j], g[2*j+1]);
                BsL[((bTk0 >> 1) + j) * LDWB + bTn] = packlo(g[2*j], g[2*j+1]);
            }
        }
    }

    for (int kt = 0; kt < nK; kt++) {
        __syncthreads();
        const int rbuf = kt & 1;
        const bool more = (kt + 1 < nK);

        // ---- prefetch next tile into regs ----
        if (more) {
            const int k0 = (kt + 1) * BK;
            #pragma unroll
            for (int i = 0; i < 4; i++)
                ra[i] = *(const float4*)(A + (long)(m0 + aRow) * lda + k0 + aK0 + 4 * i);
            if (!transB) {
                #pragma unroll
                for (int i = 0; i < 4; i++)
                    rb[i] = *(const float4*)(B + (long)(k0 + bKr0 + i) * ldb + n0 + (bNq << 2));
            } else {
                #pragma unroll
                for (int i = 0; i < 4; i++)
                    rb[i] = *(const float4*)(B + (long)(n0 + bTn) * ldb + k0 + bTk0 + 4 * i);
            }
        }

        // ---- compute from buf rbuf ----
        const unsigned* AH = AsH + rbuf * A_BUF_W;
        const unsigned* AL = AsL + rbuf * A_BUF_W;
        const unsigned* BH = BsH + rbuf * B_BUF_W;
        const unsigned* BL = BsL + rbuf * B_BUF_W;
        #pragma unroll
        for (int s = 0; s < 2; s++) {
            unsigned aH[4][4], aL[4][4], bHf[4][2], bLf[4][2];
            const int wb = s * 8 + lc;
            #pragma unroll
            for (int mt = 0; mt < 4; mt++) {
                const int r0 = (wm * 64 + mt * 16 + lr) * LDWA;
                aH[mt][0] = AH[r0 + wb];              aH[mt][1] = AH[r0 + 8 * LDWA + wb];
                aH[mt][2] = AH[r0 + wb + 4];          aH[mt][3] = AH[r0 + 8 * LDWA + wb + 4];
                aL[mt][0] = AL[r0 + wb];              aL[mt][1] = AL[r0 + 8 * LDWA + wb];
                aL[mt][2] = AL[r0 + wb + 4];          aL[mt][3] = AL[r0 + 8 * LDWA + wb + 4];
            }
            #pragma unroll
            for (int nt = 0; nt < 4; nt++) {
                const int cn = wn * 32 + nt * 8 + lr;
                bHf[nt][0] = BH[(s * 8 + lc) * LDWB + cn];
                bHf[nt][1] = BH[(s * 8 + lc + 4) * LDWB + cn];
                bLf[nt][0] = BL[(s * 8 + lc) * LDWB + cn];
                bLf[nt][1] = BL[(s * 8 + lc + 4) * LDWB + cn];
            }
            #pragma unroll
            for (int mt = 0; mt < 4; mt++)
                #pragma unroll
                for (int nt = 0; nt < 4; nt++) {
                    mma_bf16(acc[mt][nt], aH[mt], bHf[nt]);
                    mma_bf16(acc[mt][nt], aL[mt], bHf[nt]);
                    mma_bf16(acc[mt][nt], aH[mt], bLf[nt]);
                }
        }

        // ---- convert+store prefetched regs -> buf rbuf^1 (no sync needed) ----
        if (more) {
            const int wbuf = rbuf ^ 1;
            const float* f = (const float*)ra;
            unsigned* dH = AsH + wbuf * A_BUF_W + aRow * LDWA + (aK0 >> 1);
            unsigned* dL = AsL + wbuf * A_BUF_W + aRow * LDWA + (aK0 >> 1);
            *(uint4*)dH       = make_uint4(pack2(f[0],f[1]), pack2(f[2],f[3]), pack2(f[4],f[5]), pack2(f[6],f[7]));
            *(uint4*)(dH + 4) = make_uint4(pack2(f[8],f[9]), pack2(f[10],f[11]), pack2(f[12],f[13]), pack2(f[14],f[15]));
            *(uint4*)dL       = make_uint4(packlo(f[0],f[1]), packlo(f[2],f[3]), packlo(f[4],f[5]), packlo(f[6],f[7]));
            *(uint4*)(dL + 4) = make_uint4(packlo(f[8],f[9]), packlo(f[10],f[11]), packlo(f[12],f[13]), packlo(f[14],f[15]));
            if (!transB) {
                const int kp0 = bKr0 >> 1;
                #pragma unroll
                for (int p = 0; p < 2; p++) {
                    float4 u = rb[2*p], v = rb[2*p+1];
                    *(uint4*)(BsH + wbuf * B_BUF_W + (kp0 + p) * LDWB + (bNq << 2)) =
                        make_uint4(pack2(u.x,v.x), pack2(u.y,v.y), pack2(u.z,v.z), pack2(u.w,v.w));
                    *(uint4*)(BsL + wbuf * B_BUF_W + (kp0 + p) * LDWB + (bNq << 2)) =
                        make_uint4(packlo(u.x,v.x), packlo(u.y,v.y), packlo(u.z,v.z), packlo(u.w,v.w));
                }
            } else {
                const float* g = (const float*)rb;
                #pragma unroll
                for (int j = 0; j < 8; j++) {
                    BsH[wbuf * B_BUF_W + ((bTk0 >> 1) + j) * LDWB + bTn] = pack2(g[2*j], g[2*j+1]);
                    BsL[wbuf * B_BUF_W + ((bTk0 >> 1) + j) * LDWB + bTn] = packlo(g[2*j], g[2*j+1]);
                }
            }
        }
    }

    // ---- epilogue ----
    #pragma unroll
    for (int mt = 0; mt < 4; mt++) {
        #pragma unroll
        for (int nt = 0; nt < 4; nt++) {
            #pragma unroll
            for (int half = 0; half < 2; half++) {
                const int r = m0 + wm * 64 + mt * 16 + lr + half * 8;
                const int cbase = n0 + wn * 32 + nt * 8 + lc * 2;
                #pragma unroll
                for (int j = 0; j < 2; j++) {
                    const int n = cbase + j;
                    const float raw = acc[mt][nt][half * 2 + j];
                    float* cp = C + (long)r * ldc + n;
                    if (mode == -1) { *cp = raw; continue; }
                    float val = raw * scale + (bias ? bias[n] : 0.0f);
                    if (mode == 0) *cp = val;
                    else if (mode == 1) {
                        const int   even = ((n & 1) == 0);
                        const float expo = (even ? (float)n : (float)(n - 1)) / (float)Dm;
                        const float ang  = (float)r / powf(10000.0f, expo);
                        *cp = val + (even ? sinf(ang) : cosf(ang));
                    } else if (mode == 2) {
                        *cp = 0.5f * val * (1.0f + erff(val * 0.70710678118654752f));
                    } else {
                        *cp += val;
                    }
                }
            }
        }
    }
}

// ---------------- split-K reduce + epilogue ----------------
__global__ __launch_bounds__(256) void reduce_k(
    const float* __restrict__ part, float* __restrict__ C,
    const float* __restrict__ bias, int M, int N, int ldc,
    int splitK, float scale, int mode)
{
    const int idx = blockIdx.x * 256 + threadIdx.x;
    if (idx >= M * N) return;
    const int m = idx / N;
    const int n = idx - m * N;
    float s = 0.f;
    for (int p = 0; p < splitK; p++) s += part[(long)p * M * N + idx];
    float val = s * scale + (bias ? bias[n] : 0.0f);
    float* cp = C + (long)m * ldc + n;
    if (mode == 0) *cp = val;
    else if (mode == 1) {
        const int   even = ((n & 1) == 0);
        const float expo = (even ? (float)n : (float)(n - 1)) / (float)Dm;
        const float ang  = (float)m / powf(10000.0f, expo);
        *cp = val + (even ? sinf(ang) : cosf(ang));
    } else if (mode == 2) {
        *cp = 0.5f * val * (1.0f + erff(val * 0.70710678118654752f));
    } else {
        *cp += val;
    }
}

// ---------------- layernorm ----------------
__global__ __launch_bounds__(256) void layernorm_k(
    const float* __restrict__ x, float* __restrict__ y,
    const float* __restrict__ g, const float* __restrict__ b)
{
    const int row = blockIdx.x;
    const float* xr = x + (long)row * Dm;
    const int t = threadIdx.x;
    __shared__ float red[256];

    float loc[8];
    float s = 0.f;
    #pragma unroll
    for (int i = 0; i < 8; i++) { loc[i] = xr[t + i * 256]; s += loc[i]; }
    red[t] = s; __syncthreads();
    for (int st = 128; st > 0; st >>= 1) { if (t < st) red[t] += red[t + st]; __syncthreads(); }
    const float mean = red[0] * (1.0f / Dm);
    __syncthreads();

    float vs = 0.f;
    #pragma unroll
    for (int i = 0; i < 8; i++) { float d = loc[i] - mean; vs += d * d; }
    red[t] = vs; __syncthreads();
    for (int st = 128; st > 0; st >>= 1) { if (t < st) red[t] += red[t + st]; __syncthreads(); }
    const float inv = rsqrtf(red[0] * (1.0f / Dm) + EPS);

    float* yr = y + (long)row * Dm;
    #pragma unroll
    for (int i = 0; i < 8; i++) {
        const int c = t + i * 256;
        yr[c] = (loc[i] - mean) * inv * g[c] + b[c];
    }
}

// ---------------- softmax (rows of 256) ----------------
__global__ __launch_bounds__(256) void softmax_k(float* __restrict__ att)
{
    const int row = blockIdx.x;
    float* p = att + (long)row * 256;
    const int t = threadIdx.x;
    __shared__ float red[256];

    float v = p[t];
    red[t] = v; __syncthreads();
    for (int st = 128; st > 0; st >>= 1) { if (t < st) red[t] = fmaxf(red[t], red[t + st]); __syncthreads(); }
    const float mx = red[0];
    __syncthreads();

    float e = expf(v - mx);
    red[t] = e; __syncthreads();
    for (int st = 128; st > 0; st >>= 1) { if (t < st) red[t] += red[t + st]; __syncthreads(); }
    p[t] = e / red[0];
}

// ---------------- head ----------------
__global__ __launch_bounds__(256) void head_k(
    const float* __restrict__ x, const float* __restrict__ hw,
    const float* __restrict__ hb, const float* __restrict__ mem,
    float* __restrict__ out, int memN)
{
    const int t = threadIdx.x;
    __shared__ float red[256];
    float s = 0.f;
    for (int i = t; i < Dm; i += 256) s += x[i] * hw[i];
    red[t] = s; __syncthreads();
    for (int st = 128; st > 0; st >>= 1) { if (t < st) red[t] += red[t + st]; __syncthreads(); }
    if (t == 0) {
        float zv = red[0] + hb[0];
        out[0] = 1.0f / (1.0f + expf(-zv));
    }
    if (t >= 1 && t <= memN) out[t] = mem[t - 1];
}

// ---------------- host launcher ----------------
static inline float* symaddr(const void* sym) {
    void* p = nullptr;
    cudaGetSymbolAddress(&p, sym);
    return (float*)p;
}

#define SMEM_BYTES (SMEM_WORDS * 4)

extern "C" void kernel_launch(void* const* d_in, const int* in_sizes, int n_in,
                              void* d_out, int out_size)
{
    const float* images = (const float*)d_in[0];
    const float* memory = (const float*)d_in[1];
    const float* wmap   = (const float*)d_in[2];
    const float* bmap   = (const float*)d_in[3];
    const float* ln1_g  = (const float*)d_in[4];
    const float* ln1_b  = (const float*)d_in[5];
    const float* qw     = (const float*)d_in[6];
    const float* qb     = (const float*)d_in[7];
    const float* kw     = (const float*)d_in[8];
    const float* kb     = (const float*)d_in[9];
    const float* vw     = (const float*)d_in[10];
    const float* vb     = (const float*)d_in[11];
    const float* ln2_g  = (const float*)d_in[12];
    const float* ln2_b  = (const float*)d_in[13];
    const float* w1     = (const float*)d_in[14];
    const float* b1     = (const float*)d_in[15];
    const float* w2     = (const float*)d_in[16];
    const float* b2     = (const float*)d_in[17];
    const float* head_w = (const float*)d_in[18];
    const float* head_b = (const float*)d_in[19];
    float* out = (float*)d_out;

    float* x   = symaddr(g_x);
    float* h   = symaddr(g_h);
    float* q   = symaddr(g_q);
    float* k   = symaddr(g_k);
    float* v   = symaddr(g_v);
    float* att = symaddr(g_att);
    float* m   = symaddr(g_m);
    float* ws  = symaddr(g_split);

    cudaFuncSetAttribute(tgemm_k, cudaFuncAttributeMaxDynamicSharedMemorySize, SMEM_BYTES);

    const float attScale = 1.0f / sqrtf((float)DH);

    // ---- patch embed (split-K=4) ----
    tgemm_k<<<dim3(Dm / BN, S / BM, 4), 256, SMEM_BYTES>>>(
        images, wmap, ws, S, Dm, INPUT_D, INPUT_D, Dm, Dm,
        0, 0, 0, nullptr, 0, 1.0f, 0, 0, 4,
        0, nullptr, nullptr, nullptr, nullptr, nullptr, nullptr);
    reduce_k<<<(S * Dm + 255) / 256, 256>>>(ws, x, bmap, S, Dm, Dm, 4, 1.0f, 1);

    for (int l = 0; l < 2; l++) {
        const long wOff  = (long)l * NH * DH * DH;
        const long bOff  = (long)l * Dm;
        const long w1Off = (long)l * Dm * MLPD;
        const long w2Off = (long)l * MLPD * Dm;

        layernorm_k<<<S, 256>>>(x, h, ln1_g + bOff, ln1_b + bOff);

        // fused q,k,v: grid.z = 48
        tgemm_k<<<dim3(DH / BN, S / BM, 3 * NH), 256, SMEM_BYTES>>>(
            h, qw + wOff, q, S, DH, DH, Dm, DH, Dm,
            DH, (long)DH * DH, DH, qb + bOff, DH, 1.0f, 0, 0, 1,
            1, kw + wOff, vw + wOff, k, v, kb + bOff, vb + bOff);

        // scores = q @ k^T / sqrt(DH)
        tgemm_k<<<dim3(S / BN, S / BM, NH), 256, SMEM_BYTES>>>(
            q, k, att, S, S, DH, Dm, Dm, S,
            DH, DH, (long)S * S, nullptr, 0, attScale, 0, 1, 1,
            0, nullptr, nullptr, nullptr, nullptr, nullptr, nullptr);

        softmax_k<<<NH * S, 256>>>(att);

        // x += att @ v
        tgemm_k<<<dim3(DH / BN, S / BM, NH), 256, SMEM_BYTES>>>(
            att, v, x, S, DH, S, S, Dm, Dm,
            (long)S * S, DH, DH, nullptr, 0, 1.0f, 3, 0, 1,
            0, nullptr, nullptr, nullptr, nullptr, nullptr, nullptr);

        layernorm_k<<<S, 256>>>(x, h, ln2_g + bOff, ln2_b + bOff);

        // m = gelu(h @ w1 + b1)
        tgemm_k<<<dim3(MLPD / BN, S / BM, 1), 256, SMEM_BYTES>>>(
            h, w1 + w1Off, m, S, MLPD, Dm, Dm, MLPD, MLPD,
            0, 0, 0, b1 + (long)l * MLPD, 0, 1.0f, 2, 0, 1,
            0, nullptr, nullptr, nullptr, nullptr, nullptr, nullptr);

        // x += m @ w2 + b2  (split-K=4)
        tgemm_k<<<dim3(Dm / BN, S / BM, 4), 256, SMEM_BYTES>>>(
            m, w2 + w2Off, ws, S, Dm, MLPD, MLPD, Dm, Dm,
            0, 0, 0, nullptr, 0, 1.0f, 0, 0, 4,
            0, nullptr, nullptr, nullptr, nullptr, nullptr, nullptr);
        reduce_k<<<(S * Dm + 255) / 256, 256>>>(ws, x, b2 + bOff, S, Dm, Dm, 4, 1.0f, 3);
    }

    int memN = in_sizes[1];
    if (memN > out_size - 1) memN = out_size - 1;
    head_k<<<1, 256>>>(x, head_w, head_b, memory, out, memN);
}

// round 6
// speedup vs baseline: 2.4931x; 1.0868x over previous
#include <cuda_runtime.h>
#include <cuda_bf16.h>
#include <math.h>
#include <stdint.h>

// ---------------- problem constants ----------------
#define S    256
#define Dm   2048
#define NH   16
#define DH   128
#define MLPD 8192
#define INPUT_D 4096
#define EPS  1e-5f

// ---------------- scratch ----------------
__device__ float g_x  [S * Dm];
__device__ float g_h  [S * Dm];
__device__ float g_q  [S * Dm];
__device__ float g_k  [S * Dm];
__device__ float g_v  [S * Dm];
__device__ float g_att[NH * S * S];
__device__ float g_m  [S * MLPD];
__device__ float g_split[4 * S * Dm];

// ---------------- bf16 split helpers ----------------
__device__ __forceinline__ float bhi(float x) { return __bfloat162float(__float2bfloat16(x)); }
__device__ __forceinline__ unsigned pack2(float a, float b) {
    __nv_bfloat162 t = __floats2bfloat162_rn(a, b);
    return *(unsigned*)&t;
}
__device__ __forceinline__ unsigned packlo(float a, float b) {
    return pack2(a - bhi(a), b - bhi(b));
}
__device__ __forceinline__ void mma_bf16(float* c, const unsigned* a, const unsigned* b) {
    asm volatile(
        "mma.sync.aligned.m16n8k16.row.col.f32.bf16.bf16.f32 "
        "{%0,%1,%2,%3}, {%4,%5,%6,%7}, {%8,%9}, {%0,%1,%2,%3};\n"
        : "+f"(c[0]), "+f"(c[1]), "+f"(c[2]), "+f"(c[3])
        : "r"(a[0]), "r"(a[1]), "r"(a[2]), "r"(a[3]), "r"(b[0]), "r"(b[1]));
}
__device__ __forceinline__ void ldm4(unsigned* r, uint32_t addr) {
    asm volatile("ldmatrix.sync.aligned.m8n8.x4.shared.b16 {%0,%1,%2,%3}, [%4];"
                 : "=r"(r[0]), "=r"(r[1]), "=r"(r[2]), "=r"(r[3]) : "r"(addr));
}
__device__ __forceinline__ uint32_t smem_u32(const void* p) {
    uint32_t a;
    asm("{ .reg .u64 t; cvta.to.shared.u64 t, %1; cvt.u32.u64 %0, t; }" : "=r"(a) : "l"(p));
    return a;
}

// ---------------- smem geometry ----------------
// Tile 128x128, BK=32. Planes hold bf16 pairs as u32: row = 16 data words + 4 pad.
#define LDWA 20
#define PLANE_B (128 * LDWA * 4)        // 10240 bytes per plane
#define BUF_B   (4 * PLANE_B)           // AH AL BH BL
#define SMEM_BYTES (2 * BUF_B)          // double buffered: 81920
#define OFF_AH 0
#define OFF_AL PLANE_B
#define OFF_BH (2 * PLANE_B)
#define OFF_BL (3 * PLANE_B)

// ---- loaders ----
__device__ __forceinline__ void ldRows(const float* __restrict__ G, long ld,
                                       int row0, int kbase, int tid, float4* r)
{
    const int rr = tid >> 1;
    const int half = (tid & 1) * 16;
    const float* src = G + (long)(row0 + rr) * ld + kbase + half;
    #pragma unroll
    for (int i = 0; i < 4; i++) r[i] = *(const float4*)(src + 4 * i);
}
__device__ __forceinline__ void stRows(char* hi, char* lo, int tid, const float4* r)
{
    const float* f = (const float*)r;
    const int w = (tid >> 1) * LDWA + (tid & 1) * 8;
    *(uint4*)(hi + 4 * w) =
        make_uint4(pack2(f[0],f[1]), pack2(f[2],f[3]), pack2(f[4],f[5]), pack2(f[6],f[7]));
    *(uint4*)(hi + 4 * (w + 4)) =
        make_uint4(pack2(f[8],f[9]), pack2(f[10],f[11]), pack2(f[12],f[13]), pack2(f[14],f[15]));
    *(uint4*)(lo + 4 * w) =
        make_uint4(packlo(f[0],f[1]), packlo(f[2],f[3]), packlo(f[4],f[5]), packlo(f[6],f[7]));
    *(uint4*)(lo + 4 * (w + 4)) =
        make_uint4(packlo(f[8],f[9]), packlo(f[10],f[11]), packlo(f[12],f[13]), packlo(f[14],f[15]));
}
// transB=0: global B[K,N]; load 32k x 128n chunk, transpose in regs
__device__ __forceinline__ void ldBT(const float* __restrict__ G, long ld,
                                     int kbase, int n0, int tid, float4* r)
{
    const int kq = tid >> 5;            // 0..7
    const int nq = tid & 31;            // 0..31
    const float* src = G + (long)(kbase + kq * 4) * ld + n0 + nq * 4;
    #pragma unroll
    for (int i = 0; i < 4; i++) r[i] = *(const float4*)(src + (long)i * ld);
}
__device__ __forceinline__ void stBT(char* hi, char* lo, int tid, const float4* r)
{
    const int kq = tid >> 5;
    const int nq = tid & 31;
    const float c[4][4] = {{r[0].x, r[1].x, r[2].x, r[3].x}, {r[0].y, r[1].y, r[2].y, r[3].y},
                           {r[0].z, r[1].z, r[2].z, r[3].z}, {r[0].w, r[1].w, r[2].w, r[3].w}};
    #pragma unroll
    for (int j = 0; j < 4; j++) {
        const int w = (nq * 4 + j) * LDWA + kq * 2;
        *(uint2*)(hi + 4 * w) = make_uint2(pack2(c[j][0], c[j][1]), pack2(c[j][2], c[j][3]));
        *(uint2*)(lo + 4 * w) = make_uint2(packlo(c[j][0], c[j][1]), packlo(c[j][2], c[j][3]));
    }
}

// ================= bf16 3-mma GEMM (ldmatrix + double buffer) =================
// modes: 0 store | 1 posemb | 2 gelu | 3 accumulate | -1 raw (splitK)
__global__ void __launch_bounds__(256, 1) tgemm_k(
    const float* __restrict__ A, const float* __restrict__ B, float* __restrict__ C,
    int M, int N, int K, int lda, int ldb, int ldc,
    long batchA, long batchB, long batchC,
    const float* __restrict__ bias, long biasBatch,
    float scale, int mode, int transB, int splitK,
    int qkv, const float* __restrict__ B1, const float* __restrict__ B2,
    float* C1, float* C2,
    const float* __restrict__ bias1, const float* __restrict__ bias2)
{
    extern __shared__ char smc[];
    const uint32_t sbase = smem_u32(smc);

    int z = blockIdx.z;
    if (qkv) {
        const int sel = z >> 4;
        z &= 15;
        if (sel == 1)      { B = B1; C = C1; bias = bias1; }
        else if (sel == 2) { B = B2; C = C2; bias = bias2; }
    }
    if (splitK > 1) {
        const int Kc = K / splitK;
        A += (long)z * Kc;
        B += transB ? (long)z * Kc : (long)z * Kc * ldb;
        C += (long)z * M * N;
        ldc = N; K = Kc; bias = nullptr; mode = -1;
    } else {
        A += (long)z * batchA;
        B += (long)z * batchB;
        C += (long)z * batchC;
        if (bias) bias += (long)z * biasBatch;
    }

    const int m0 = blockIdx.y * 128;
    const int n0 = blockIdx.x * 128;
    const int tid  = threadIdx.x;
    const int lane = tid & 31;
    const int warp = tid >> 5;
    const int wm = warp >> 2;          // 0..1 (64 rows)
    const int wn = warp & 3;           // 0..3 (32 cols)
    const int lr = lane >> 2;
    const int lc = lane & 3;

    float acc[4][4][4];
    #pragma unroll
    for (int i = 0; i < 4; i++)
        #pragma unroll
        for (int j = 0; j < 4; j++)
            #pragma unroll
            for (int r = 0; r < 4; r++) acc[i][j][r] = 0.f;

    // ldmatrix per-lane byte offsets (within a plane)
    uint32_t aOff[4], bOff[2];
    {
        const int arow = (lane & 7) + ((lane >> 3) & 1) * 8;
        const int akw  = ((lane >> 4) & 1) * 4;
        #pragma unroll
        for (int mt = 0; mt < 4; mt++)
            aOff[mt] = ((wm * 64 + mt * 16 + arow) * LDWA + akw) * 4;
        const int brow = (lane & 7) + ((lane >> 4) & 1) * 8;
        const int bkw  = ((lane >> 3) & 1) * 4;
        #pragma unroll
        for (int p = 0; p < 2; p++)
            bOff[p] = ((wn * 32 + p * 16 + brow) * LDWA + bkw) * 4;
    }

    float4 ra[4], rb[4];
    const int nCh = K >> 5;

    // prologue: chunk 0 -> regs -> buf0
    ldRows(A, lda, m0, 0, tid, ra);
    if (transB) ldRows(B, ldb, n0, 0, tid, rb);
    else        ldBT(B, ldb, 0, n0, tid, rb);
    stRows(smc + OFF_AH, smc + OFF_AL, tid, ra);
    if (transB) stRows(smc + OFF_BH, smc + OFF_BL, tid, rb);
    else        stBT(smc + OFF_BH, smc + OFF_BL, tid, rb);

    for (int c = 0; c < nCh; c++) {
        __syncthreads();
        const int rbuf = c & 1;
        const bool more = (c + 1 < nCh);

        if (more) {
            const int kb = (c + 1) * 32;
            ldRows(A, lda, m0, kb, tid, ra);
            if (transB) ldRows(B, ldb, n0, kb, tid, rb);
            else        ldBT(B, ldb, kb, n0, tid, rb);
        }

        const uint32_t bb = sbase + rbuf * BUF_B;
        #pragma unroll
        for (int s = 0; s < 2; s++) {
            const uint32_t so = s * 32;
            unsigned aH[4][4], aL[4][4], bH[2][4], bL[2][4];
            #pragma unroll
            for (int mt = 0; mt < 4; mt++) {
                ldm4(aH[mt], bb + OFF_AH + aOff[mt] + so);
                ldm4(aL[mt], bb + OFF_AL + aOff[mt] + so);
            }
            #pragma unroll
            for (int p = 0; p < 2; p++) {
                ldm4(bH[p], bb + OFF_BH + bOff[p] + so);
                ldm4(bL[p], bb + OFF_BL + bOff[p] + so);
            }
            #pragma unroll
            for (int mt = 0; mt < 4; mt++)
                #pragma unroll
                for (int nt = 0; nt < 4; nt++) {
                    const unsigned* bh = &bH[nt >> 1][(nt & 1) * 2];
                    const unsigned* bl = &bL[nt >> 1][(nt & 1) * 2];
                    mma_bf16(acc[mt][nt], aH[mt], bh);
                    mma_bf16(acc[mt][nt], aL[mt], bh);
                    mma_bf16(acc[mt][nt], aH[mt], bl);
                }
        }

        if (more) {
            char* wb = smc + (rbuf ^ 1) * BUF_B;
            stRows(wb + OFF_AH, wb + OFF_AL, tid, ra);
            if (transB) stRows(wb + OFF_BH, wb + OFF_BL, tid, rb);
            else        stBT(wb + OFF_BH, wb + OFF_BL, tid, rb);
        }
    }

    // ---- epilogue ----
    #pragma unroll
    for (int mt = 0; mt < 4; mt++) {
        #pragma unroll
        for (int nt = 0; nt < 4; nt++) {
            #pragma unroll
            for (int half = 0; half < 2; half++) {
                const int r = m0 + wm * 64 + mt * 16 + lr + half * 8;
                const int cbase = n0 + wn * 32 + nt * 8 + lc * 2;
                #pragma unroll
                for (int j = 0; j < 2; j++) {
                    const int n = cbase + j;
                    const float raw = acc[mt][nt][half * 2 + j];
                    float* cp = C + (long)r * ldc + n;
                    if (mode == -1) { *cp = raw; continue; }
                    float val = raw * scale + (bias ? bias[n] : 0.0f);
                    if (mode == 0) *cp = val;
                    else if (mode == 1) {
                        const int   even = ((n & 1) == 0);
                        const float expo = (even ? (float)n : (float)(n - 1)) / (float)Dm;
                        const float ang  = (float)r / powf(10000.0f, expo);
                        *cp = val + (even ? sinf(ang) : cosf(ang));
                    } else if (mode == 2) {
                        *cp = 0.5f * val * (1.0f + erff(val * 0.70710678118654752f));
                    } else {
                        *cp += val;
                    }
                }
            }
        }
    }
}

// ---------------- split-K reduce + epilogue ----------------
__global__ __launch_bounds__(256) void reduce_k(
    const float* __restrict__ part, float* __restrict__ C,
    const float* __restrict__ bias, int M, int N, int ldc,
    int splitK, float scale, int mode)
{
    const int idx = blockIdx.x * 256 + threadIdx.x;
    if (idx >= M * N) return;
    const int m = idx / N;
    const int n = idx - m * N;
    float s = 0.f;
    for (int p = 0; p < splitK; p++) s += part[(long)p * M * N + idx];
    float val = s * scale + (bias ? bias[n] : 0.0f);
    float* cp = C + (long)m * ldc + n;
    if (mode == 0) *cp = val;
    else if (mode == 1) {
        const int   even = ((n & 1) == 0);
        const float expo = (even ? (float)n : (float)(n - 1)) / (float)Dm;
        const float ang  = (float)m / powf(10000.0f, expo);
        *cp = val + (even ? sinf(ang) : cosf(ang));
    } else if (mode == 2) {
        *cp = 0.5f * val * (1.0f + erff(val * 0.70710678118654752f));
    } else {
        *cp += val;
    }
}

// ---------------- layernorm ----------------
__global__ __launch_bounds__(256) void layernorm_k(
    const float* __restrict__ x, float* __restrict__ y,
    const float* __restrict__ g, const float* __restrict__ b)
{
    const int row = blockIdx.x;
    const float* xr = x + (long)row * Dm;
    const int t = threadIdx.x;
    __shared__ float red[256];

    float loc[8];
    float s = 0.f;
    #pragma unroll
    for (int i = 0; i < 8; i++) { loc[i] = xr[t + i * 256]; s += loc[i]; }
    red[t] = s; __syncthreads();
    for (int st = 128; st > 0; st >>= 1) { if (t < st) red[t] += red[t + st]; __syncthreads(); }
    const float mean = red[0] * (1.0f / Dm);
    __syncthreads();

    float vs = 0.f;
    #pragma unroll
    for (int i = 0; i < 8; i++) { float d = loc[i] - mean; vs += d * d; }
    red[t] = vs; __syncthreads();
    for (int st = 128; st > 0; st >>= 1) { if (t < st) red[t] += red[t + st]; __syncthreads(); }
    const float inv = rsqrtf(red[0] * (1.0f / Dm) + EPS);

    float* yr = y + (long)row * Dm;
    #pragma unroll
    for (int i = 0; i < 8; i++) {
        const int c = t + i * 256;
        yr[c] = (loc[i] - mean) * inv * g[c] + b[c];
    }
}

// ---------------- softmax (rows of 256) ----------------
__global__ __launch_bounds__(256) void softmax_k(float* __restrict__ att)
{
    const int row = blockIdx.x;
    float* p = att + (long)row * 256;
    const int t = threadIdx.x;
    __shared__ float red[256];

    float v = p[t];
    red[t] = v; __syncthreads();
    for (int st = 128; st > 0; st >>= 1) { if (t < st) red[t] = fmaxf(red[t], red[t + st]); __syncthreads(); }
    const float mx = red[0];
    __syncthreads();

    float e = expf(v - mx);
    red[t] = e; __syncthreads();
    for (int st = 128; st > 0; st >>= 1) { if (t < st) red[t] += red[t + st]; __syncthreads(); }
    p[t] = e / red[0];
}

// ---------------- head ----------------
__global__ __launch_bounds__(256) void head_k(
    const float* __restrict__ x, const float* __restrict__ hw,
    const float* __restrict__ hb, const float* __restrict__ mem,
    float* __restrict__ out, int memN)
{
    const int t = threadIdx.x;
    __shared__ float red[256];
    float s = 0.f;
    for (int i = t; i < Dm; i += 256) s += x[i] * hw[i];
    red[t] = s; __syncthreads();
    for (int st = 128; st > 0; st >>= 1) { if (t < st) red[t] += red[t + st]; __syncthreads(); }
    if (t == 0) {
        float zv = red[0] + hb[0];
        out[0] = 1.0f / (1.0f + expf(-zv));
    }
    if (t >= 1 && t <= memN) out[t] = mem[t - 1];
}

// ---------------- host launcher ----------------
static inline float* symaddr(const void* sym) {
    void* p = nullptr;
    cudaGetSymbolAddress(&p, sym);
    return (float*)p;
}

extern "C" void kernel_launch(void* const* d_in, const int* in_sizes, int n_in,
                              void* d_out, int out_size)
{
    const float* images = (const float*)d_in[0];
    const float* memory = (const float*)d_in[1];
    const float* wmap   = (const float*)d_in[2];
    const float* bmap   = (const float*)d_in[3];
    const float* ln1_g  = (const float*)d_in[4];
    const float* ln1_b  = (const float*)d_in[5];
    const float* qw     = (const float*)d_in[6];
    const float* qb     = (const float*)d_in[7];
    const float* kw     = (const float*)d_in[8];
    const float* kb     = (const float*)d_in[9];
    const float* vw     = (const float*)d_in[10];
    const float* vb     = (const float*)d_in[11];
    const float* ln2_g  = (const float*)d_in[12];
    const float* ln2_b  = (const float*)d_in[13];
    const float* w1     = (const float*)d_in[14];
    const float* b1     = (const float*)d_in[15];
    const float* w2     = (const float*)d_in[16];
    const float* b2     = (const float*)d_in[17];
    const float* head_w = (const float*)d_in[18];
    const float* head_b = (const float*)d_in[19];
    float* out = (float*)d_out;

    float* x   = symaddr(g_x);
    float* h   = symaddr(g_h);
    float* q   = symaddr(g_q);
    float* k   = symaddr(g_k);
    float* v   = symaddr(g_v);
    float* att = symaddr(g_att);
    float* m   = symaddr(g_m);
    float* ws  = symaddr(g_split);

    cudaFuncSetAttribute(tgemm_k, cudaFuncAttributeMaxDynamicSharedMemorySize, SMEM_BYTES);

    const float attScale = 1.0f / sqrtf((float)DH);

    // ---- patch embed (split-K=4): 16 x 2 x 4 = 128 CTAs ----
    tgemm_k<<<dim3(Dm / 128, S / 128, 4), 256, SMEM_BYTES>>>(
        images, wmap, ws, S, Dm, INPUT_D, INPUT_D, Dm, Dm,
        0, 0, 0, nullptr, 0, 1.0f, 0, 0, 4,
        0, nullptr, nullptr, nullptr, nullptr, nullptr, nullptr);
    reduce_k<<<(S * Dm + 255) / 256, 256>>>(ws, x, bmap, S, Dm, Dm, 4, 1.0f, 1);

    for (int l = 0; l < 2; l++) {
        const long wOff  = (long)l * NH * DH * DH;
        const long bOff  = (long)l * Dm;
        const long w1Off = (long)l * Dm * MLPD;
        const long w2Off = (long)l * MLPD * Dm;

        layernorm_k<<<S, 256>>>(x, h, ln1_g + bOff, ln1_b + bOff);

        // fused q,k,v: grid 1 x 2 x 48 = 96 CTAs
        tgemm_k<<<dim3(DH / 128, S / 128, 3 * NH), 256, SMEM_BYTES>>>(
            h, qw + wOff, q, S, DH, DH, Dm, DH, Dm,
            DH, (long)DH * DH, DH, qb + bOff, DH, 1.0f, 0, 0, 1,
            1, kw + wOff, vw + wOff, k, v, kb + bOff, vb + bOff);

        // scores = q @ k^T / sqrt(DH): grid 2 x 2 x 16 = 64
        tgemm_k<<<dim3(S / 128, S / 128, NH), 256, SMEM_BYTES>>>(
            q, k, att, S, S, DH, Dm, Dm, S,
            DH, DH, (long)S * S, nullptr, 0, attScale, 0, 1, 1,
            0, nullptr, nullptr, nullptr, nullptr, nullptr, nullptr);

        softmax_k<<<NH * S, 256>>>(att);

        // x += att @ v: grid 1 x 2 x 16 = 32
        tgemm_k<<<dim3(DH / 128, S / 128, NH), 256, SMEM_BYTES>>>(
            att, v, x, S, DH, S, S, Dm, Dm,
            (long)S * S, DH, DH, nullptr, 0, 1.0f, 3, 0, 1,
            0, nullptr, nullptr, nullptr, nullptr, nullptr, nullptr);

        layernorm_k<<<S, 256>>>(x, h, ln2_g + bOff, ln2_b + bOff);

        // m = gelu(h @ w1 + b1): grid 64 x 2 = 128, direct epilogue
        tgemm_k<<<dim3(MLPD / 128, S / 128, 1), 256, SMEM_BYTES>>>(
            h, w1 + w1Off, m, S, MLPD, Dm, Dm, MLPD, MLPD,
            0, 0, 0, b1 + (long)l * MLPD, 0, 1.0f, 2, 0, 1,
            0, nullptr, nullptr, nullptr, nullptr, nullptr, nullptr);

        // x += m @ w2 + b2: split-K=4 -> 16 x 2 x 4 = 128
        tgemm_k<<<dim3(Dm / 128, S / 128, 4), 256, SMEM_BYTES>>>(
            m, w2 + w2Off, ws, S, Dm, MLPD, MLPD, Dm, Dm,
            0, 0, 0, nullptr, 0, 1.0f, 0, 0, 4,
            0, nullptr, nullptr, nullptr, nullptr, nullptr, nullptr);
        reduce_k<<<(S * Dm + 255) / 256, 256>>>(ws, x, b2 + bOff, S, Dm, Dm, 4, 1.0f, 3);
    }

    int memN = in_sizes[1];
    if (memN > out_size - 1) memN = out_size - 1;
    head_k<<<1, 256>>>(x, head_w, head_b, memory, out, memN);
}